// round 1
// baseline (speedup 1.0000x reference)
#include <cuda_runtime.h>
#include <math.h>

// Problem constants (fixed by reference setup)
#define NWIN  2048          // number of windows / rows n
#define LTOK  64            // tokens per window
#define ATOK  48            // asy tokens per window
#define CDIM  256
#define HEADS 8
#define DH    32
#define AROWS (NWIN*ATOK)   // 98304 asy rows
#define QKSCALE 0.17677669529663687f  // 32^-0.5
#define LNEPS 1e-5f

// ---------------- scratch (device globals; no runtime allocation) ------------
__device__ float g_z  [AROWS*CDIM];   // LN2(LN1(x)) for asy tokens
__device__ float g_qkv[AROWS*768];
__device__ float g_ao [AROWS*CDIM];   // attention output (pre-proj)
__device__ float g_xa [AROWS*CDIM];   // z + ls1*proj(o)
__device__ float g_h1 [AROWS*1024];   // gelu(mlp1)
__device__ float g_mm [AROWS*CDIM];   // mlp2 out
__device__ float g_part[8*32*CDIM];   // chunk partial sums
__device__ float g_cmean[8*CDIM];     // chunk means

__device__ __forceinline__ float wsum(float v){
#pragma unroll
    for (int o = 16; o > 0; o >>= 1) v += __shfl_xor_sync(0xffffffffu, v, o);
    return v;
}

// ---------------- Kernel 1: fused LN1 (+LN2 for asy rows) --------------------
// one warp per row of x (131072 rows). p>=48 rows -> d_out directly.
__global__ __launch_bounds__(256) void ln_kernel(
    const float* __restrict__ x,
    const float* __restrict__ g1, const float* __restrict__ b1,
    const float* __restrict__ g2, const float* __restrict__ b2,
    float* __restrict__ out)
{
    int warp = threadIdx.x >> 5, lane = threadIdx.x & 31;
    int row = blockIdx.x * 8 + warp;              // 0..131071
    const float* xr = x + (size_t)row * CDIM;
    int c0 = lane * 4;

    float v[8];
    {
        float4 a = *(const float4*)(xr + c0);
        float4 b = *(const float4*)(xr + 128 + c0);
        v[0]=a.x; v[1]=a.y; v[2]=a.z; v[3]=a.w;
        v[4]=b.x; v[5]=b.y; v[6]=b.z; v[7]=b.w;
    }
    float s = 0;
#pragma unroll
    for (int i = 0; i < 8; i++) s += v[i];
    float mu = wsum(s) * (1.f/256.f);
    float q = 0;
#pragma unroll
    for (int i = 0; i < 8; i++) { v[i] -= mu; q += v[i]*v[i]; }
    float rstd = rsqrtf(wsum(q) * (1.f/256.f) + LNEPS);

    float gg[8], bb[8];
    {
        float4 a = *(const float4*)(g1 + c0);
        float4 b = *(const float4*)(g1 + 128 + c0);
        gg[0]=a.x; gg[1]=a.y; gg[2]=a.z; gg[3]=a.w; gg[4]=b.x; gg[5]=b.y; gg[6]=b.z; gg[7]=b.w;
        float4 c = *(const float4*)(b1 + c0);
        float4 d = *(const float4*)(b1 + 128 + c0);
        bb[0]=c.x; bb[1]=c.y; bb[2]=c.z; bb[3]=c.w; bb[4]=d.x; bb[5]=d.y; bb[6]=d.z; bb[7]=d.w;
    }
    float y[8];
#pragma unroll
    for (int i = 0; i < 8; i++) y[i] = v[i]*rstd*gg[i] + bb[i];

    int p = row & 63, n = row >> 6;
    if (p >= ATOK) {
        float* o = out + (size_t)row * CDIM;
        float4 a = make_float4(y[0],y[1],y[2],y[3]);
        float4 b = make_float4(y[4],y[5],y[6],y[7]);
        *(float4*)(o + c0) = a;
        *(float4*)(o + 128 + c0) = b;
    } else {
        // second LN on y
        float s2 = 0;
#pragma unroll
        for (int i = 0; i < 8; i++) s2 += y[i];
        float mu2 = wsum(s2) * (1.f/256.f);
        float q2 = 0;
#pragma unroll
        for (int i = 0; i < 8; i++) { y[i] -= mu2; q2 += y[i]*y[i]; }
        float rstd2 = rsqrtf(wsum(q2) * (1.f/256.f) + LNEPS);
        float g2v[8], b2v[8];
        {
            float4 a = *(const float4*)(g2 + c0);
            float4 b = *(const float4*)(g2 + 128 + c0);
            g2v[0]=a.x; g2v[1]=a.y; g2v[2]=a.z; g2v[3]=a.w; g2v[4]=b.x; g2v[5]=b.y; g2v[6]=b.z; g2v[7]=b.w;
            float4 c = *(const float4*)(b2 + c0);
            float4 d = *(const float4*)(b2 + 128 + c0);
            b2v[0]=c.x; b2v[1]=c.y; b2v[2]=c.z; b2v[3]=c.w; b2v[4]=d.x; b2v[5]=d.y; b2v[6]=d.z; b2v[7]=d.w;
        }
        float z[8];
#pragma unroll
        for (int i = 0; i < 8; i++) z[i] = y[i]*rstd2*g2v[i] + b2v[i];
        float* o = g_z + ((size_t)n*ATOK + p) * CDIM;
        *(float4*)(o + c0)       = make_float4(z[0],z[1],z[2],z[3]);
        *(float4*)(o + 128 + c0) = make_float4(z[4],z[5],z[6],z[7]);
    }
}

// ---------------- Kernel 2: SGEMM 128x128x8, 8x8/thread, fused epilogues -----
// EPI: 0 = +bias; 1 = gelu(+bias); 2 = res + lsc*(+bias)
template<int EPI>
__global__ __launch_bounds__(256) void sgemm128(
    const float* __restrict__ A, const float* __restrict__ Bw,
    const float* __restrict__ bias, float* __restrict__ C,
    int K, int N,
    const float* __restrict__ res, const float* __restrict__ lsc)
{
    __shared__ float As[8][128];
    __shared__ float Bs[8][128];
    int tid = threadIdx.x;
    int row0 = blockIdx.y * 128;
    int col0 = blockIdx.x * 128;

    int arow = tid >> 1;            // 0..127
    int acol = (tid & 1) * 4;       // 0 or 4
    int brow = tid >> 5;            // 0..7
    int bcol = (tid & 31) * 4;      // 0..124
    int tx = tid & 15, ty = tid >> 4;

    float acc[8][8] = {};
    for (int k0 = 0; k0 < K; k0 += 8) {
        float4 av = *(const float4*)&A[(size_t)(row0 + arow) * K + k0 + acol];
        float4 bv = *(const float4*)&Bw[(size_t)(k0 + brow) * N + col0 + bcol];
        As[acol+0][arow] = av.x; As[acol+1][arow] = av.y;
        As[acol+2][arow] = av.z; As[acol+3][arow] = av.w;
        *(float4*)&Bs[brow][bcol] = bv;
        __syncthreads();
#pragma unroll
        for (int kk = 0; kk < 8; kk++) {
            float ar[8], br[8];
            *(float4*)&ar[0] = *(float4*)&As[kk][ty*8];
            *(float4*)&ar[4] = *(float4*)&As[kk][ty*8+4];
            *(float4*)&br[0] = *(float4*)&Bs[kk][tx*8];
            *(float4*)&br[4] = *(float4*)&Bs[kk][tx*8+4];
#pragma unroll
            for (int i = 0; i < 8; i++)
#pragma unroll
                for (int j = 0; j < 8; j++)
                    acc[i][j] = fmaf(ar[i], br[j], acc[i][j]);
        }
        __syncthreads();
    }

    float bsv[8];
#pragma unroll
    for (int j = 0; j < 8; j++) bsv[j] = bias[col0 + tx*8 + j];

#pragma unroll
    for (int i = 0; i < 8; i++) {
        int row = row0 + ty*8 + i;
        size_t base = (size_t)row * N;
#pragma unroll
        for (int j = 0; j < 8; j++) {
            int c = col0 + tx*8 + j;
            float vv = acc[i][j] + bsv[j];
            if (EPI == 1) {
                vv = 0.5f * vv * (1.f + erff(vv * 0.70710678118654752f));
            } else if (EPI == 2) {
                vv = res[base + c] + lsc[c] * vv;
            }
            C[base + c] = vv;
        }
    }
}

// ---------------- Kernel 3: per-(n,head) 48x48 attention ---------------------
__global__ __launch_bounds__(128) void attn_kernel(
    const float* __restrict__ qkv, float* __restrict__ ao)
{
    __shared__ float qs[48][33], ks[48][33], vs[48][33], S[48][49];
    int blk = blockIdx.x;
    int n = blk >> 3, h = blk & 7;
    int tid = threadIdx.x;
    const float* base = qkv + (size_t)n*ATOK*768 + h*96;

    for (int idx = tid; idx < 48*96; idx += 128) {
        int p = idx / 96, c = idx - p*96;
        float v = base[(size_t)p*768 + c];
        if (c < 32)       qs[p][c]    = v;
        else if (c < 64)  ks[p][c-32] = v;
        else              vs[p][c-64] = v;
    }
    __syncthreads();

    {   // S = q k^T * scale ; thread tile 3x6
        int ti = tid >> 3, tj = tid & 7;
        float acc[3][6] = {};
#pragma unroll
        for (int d = 0; d < 32; d++) {
            float aq[3], bk[6];
#pragma unroll
            for (int ii = 0; ii < 3; ii++) aq[ii] = qs[ti*3+ii][d];
#pragma unroll
            for (int jj = 0; jj < 6; jj++) bk[jj] = ks[tj*6+jj][d];
#pragma unroll
            for (int ii = 0; ii < 3; ii++)
#pragma unroll
                for (int jj = 0; jj < 6; jj++)
                    acc[ii][jj] = fmaf(aq[ii], bk[jj], acc[ii][jj]);
        }
#pragma unroll
        for (int ii = 0; ii < 3; ii++)
#pragma unroll
            for (int jj = 0; jj < 6; jj++)
                S[ti*3+ii][tj*6+jj] = acc[ii][jj] * QKSCALE;
    }
    __syncthreads();

    if (tid < 48) {   // softmax over 48 keys
        float m = -1e30f;
#pragma unroll 4
        for (int j = 0; j < 48; j++) m = fmaxf(m, S[tid][j]);
        float s = 0.f;
#pragma unroll 4
        for (int j = 0; j < 48; j++) { float e = __expf(S[tid][j] - m); S[tid][j] = e; s += e; }
        float inv = 1.f / s;
#pragma unroll 4
        for (int j = 0; j < 48; j++) S[tid][j] *= inv;
    }
    __syncthreads();

    {   // O = S @ v ; thread tile 3x4
        int ti = tid >> 3, td = tid & 7;
        float acc[3][4] = {};
#pragma unroll 4
        for (int j = 0; j < 48; j++) {
            float sv[3], vv[4];
#pragma unroll
            for (int ii = 0; ii < 3; ii++) sv[ii] = S[ti*3+ii][j];
#pragma unroll
            for (int dd = 0; dd < 4; dd++) vv[dd] = vs[j][td*4+dd];
#pragma unroll
            for (int ii = 0; ii < 3; ii++)
#pragma unroll
                for (int dd = 0; dd < 4; dd++)
                    acc[ii][dd] = fmaf(sv[ii], vv[dd], acc[ii][dd]);
        }
#pragma unroll
        for (int ii = 0; ii < 3; ii++)
#pragma unroll
            for (int dd = 0; dd < 4; dd++)
                ao[((size_t)n*ATOK + ti*3+ii)*CDIM + h*DH + td*4+dd] = acc[ii][dd];
    }
}

// ---------------- Kernel 4/5: cross-block chunk means ------------------------
__global__ __launch_bounds__(256) void chunk_partial(
    const float* __restrict__ mm, float* __restrict__ part)
{
    int b = blockIdx.y, s = blockIdx.x;       // 8 chunks x 32 slices
    int c = threadIdx.x;
    size_t r0 = (size_t)b * 12288 + (size_t)s * 384;
    float acc = 0.f;
    for (int r = 0; r < 384; r++) acc += mm[(r0 + r) * CDIM + c];
    part[((size_t)b*32 + s) * CDIM + c] = acc;
}

__global__ __launch_bounds__(256) void chunk_reduce(
    const float* __restrict__ part, float* __restrict__ cmean)
{
    int b = blockIdx.x, c = threadIdx.x;
    float a = 0.f;
#pragma unroll
    for (int s = 0; s < 32; s++) a += part[((size_t)b*32 + s) * CDIM + c];
    cmean[b*CDIM + c] = a * (1.f / 16384.f);
}

// ---------------- Kernel 6: final combine for asy rows -----------------------
__global__ __launch_bounds__(256) void final_kernel(
    const float* __restrict__ xa, const float* __restrict__ mm,
    const float* __restrict__ cmean, const float* __restrict__ ls2,
    float* __restrict__ out)
{
    int row = blockIdx.x;             // 0..98303
    int c = threadIdx.x;
    int n = row / ATOK, p = row - n * ATOK;
    int b = row / 12288;              // chunk = n/256
    float m = 0.5f * mm[(size_t)row*CDIM + c] + 0.5f * cmean[b*CDIM + c];
    out[((size_t)n*LTOK + p)*CDIM + c] = xa[(size_t)row*CDIM + c] + ls2[c] * m;
}

// ---------------- host launch ------------------------------------------------
extern "C" void kernel_launch(void* const* d_in, const int* in_sizes, int n_in,
                              void* d_out, int out_size)
{
    const float* x      = (const float*)d_in[0];
    const float* n1g    = (const float*)d_in[8];
    const float* n1b    = (const float*)d_in[9];
    const float* n2g    = (const float*)d_in[10];
    const float* n2b    = (const float*)d_in[11];
    const float* qkvw   = (const float*)d_in[12];
    const float* qkvb   = (const float*)d_in[13];
    const float* projw  = (const float*)d_in[14];
    const float* projb  = (const float*)d_in[15];
    const float* ls1    = (const float*)d_in[16];
    const float* ls2    = (const float*)d_in[17];
    const float* w1     = (const float*)d_in[18];
    const float* b1     = (const float*)d_in[19];
    const float* w2     = (const float*)d_in[20];
    const float* b2     = (const float*)d_in[21];
    float* out = (float*)d_out;

    float *pz, *pqkv, *pao, *pxa, *ph1, *pmm, *ppart, *pcmean;
    cudaGetSymbolAddress((void**)&pz,    g_z);
    cudaGetSymbolAddress((void**)&pqkv,  g_qkv);
    cudaGetSymbolAddress((void**)&pao,   g_ao);
    cudaGetSymbolAddress((void**)&pxa,   g_xa);
    cudaGetSymbolAddress((void**)&ph1,   g_h1);
    cudaGetSymbolAddress((void**)&pmm,   g_mm);
    cudaGetSymbolAddress((void**)&ppart, g_part);
    cudaGetSymbolAddress((void**)&pcmean,g_cmean);

    // 1) LN1 (+LN2 for asy rows); writes padding rows of output directly
    ln_kernel<<<16384, 256>>>(x, n1g, n1b, n2g, n2b, out);
    // 2) QKV GEMM: [98304,256] x [256,768]
    sgemm128<0><<<dim3(6, 768), 256>>>(pz, qkvw, qkvb, pqkv, 256, 768, nullptr, nullptr);
    // 3) attention per (n, head)
    attn_kernel<<<NWIN * HEADS, 128>>>(pqkv, pao);
    // 4) proj GEMM + residual/layerscale: xa = z + ls1*(ao@Wp + bp)
    sgemm128<2><<<dim3(2, 768), 256>>>(pao, projw, projb, pxa, 256, 256, pz, ls1);
    // 5) MLP1 + gelu
    sgemm128<1><<<dim3(8, 768), 256>>>(pxa, w1, b1, ph1, 256, 1024, nullptr, nullptr);
    // 6) MLP2
    sgemm128<0><<<dim3(2, 768), 256>>>(ph1, w2, b2, pmm, 1024, 256, nullptr, nullptr);
    // 7) cross-block chunk means
    chunk_partial<<<dim3(32, 8), 256>>>(pmm, ppart);
    chunk_reduce<<<8, 256>>>(ppart, pcmean);
    // 8) final combine for asy rows
    final_kernel<<<AROWS, 256>>>(pxa, pmm, pcmean, ls2, out);
}

// round 3
// speedup vs baseline: 3.8824x; 3.8824x over previous
#include <cuda_runtime.h>
#include <cuda_bf16.h>
#include <math.h>
#include <stdint.h>

// Problem constants
#define NWIN  2048
#define LTOK  64
#define ATOK  48
#define CDIM  256
#define HEADS 8
#define DH    32
#define AROWS (NWIN*ATOK)       // 98304
#define QKSCALE 0.17677669529663687f
#define LNEPS 1e-5f

// ---------------- scratch (device globals) -----------------------------------
__device__ float          g_z  [AROWS*CDIM];    // LN2 out fp32 (residual)
__device__ __nv_bfloat16  g_zb [AROWS*CDIM];    // LN2 out bf16 (GEMM A)
__device__ __nv_bfloat16  g_qkv[AROWS*768];     // QKV out bf16
__device__ __nv_bfloat16  g_aob[AROWS*CDIM];    // attn out bf16
__device__ float          g_xa [AROWS*CDIM];    // xa fp32
__device__ __nv_bfloat16  g_xab[AROWS*CDIM];    // xa bf16 (MLP A)
__device__ __nv_bfloat16  g_h1b[AROWS*1024];    // gelu(mlp1) bf16
__device__ float          g_mm [AROWS*CDIM];    // mlp2 out fp32
__device__ float          g_part[8*32*CDIM];
__device__ float          g_cmean[8*CDIM];
// transposed bf16 weights [N,K] (K-major)
__device__ __nv_bfloat16  g_wqkvt[768*256];
__device__ __nv_bfloat16  g_wprot[256*256];
__device__ __nv_bfloat16  g_w1t  [1024*256];
__device__ __nv_bfloat16  g_w2t  [256*1024];

// ---------------- helpers ------------------------------------------------------
__device__ __forceinline__ uint32_t smem_u32(const void* p) {
    uint32_t a;
    asm("{ .reg .u64 t; cvta.to.shared.u64 t, %1; cvt.u32.u64 %0, t; }" : "=r"(a) : "l"(p));
    return a;
}
__device__ __forceinline__ void cpa16(uint32_t s, const void* g) {
    asm volatile("cp.async.cg.shared.global [%0], [%1], 16;" :: "r"(s), "l"(g) : "memory");
}
__device__ __forceinline__ void ldsm4(uint32_t& r0, uint32_t& r1, uint32_t& r2, uint32_t& r3,
                                      uint32_t addr) {
    asm volatile("ldmatrix.sync.aligned.m8n8.x4.shared.b16 {%0,%1,%2,%3}, [%4];"
        : "=r"(r0), "=r"(r1), "=r"(r2), "=r"(r3) : "r"(addr));
}
__device__ __forceinline__ void mma16816(float* d, const uint32_t* a, const uint32_t* b) {
    asm volatile(
        "mma.sync.aligned.m16n8k16.row.col.f32.bf16.bf16.f32 "
        "{%0,%1,%2,%3}, {%4,%5,%6,%7}, {%8,%9}, {%0,%1,%2,%3};"
        : "+f"(d[0]), "+f"(d[1]), "+f"(d[2]), "+f"(d[3])
        : "r"(a[0]), "r"(a[1]), "r"(a[2]), "r"(a[3]), "r"(b[0]), "r"(b[1]));
}
// swizzled byte offset inside a [128 rows x 32 bf16] tile (row = 64B, 4x16B chunks)
__device__ __forceinline__ uint32_t swoff(int r, int c) {
    return (uint32_t)(r * 64 + ((c ^ ((r >> 1) & 3)) << 4));
}
__device__ __forceinline__ float wsum(float v) {
#pragma unroll
    for (int o = 16; o > 0; o >>= 1) v += __shfl_xor_sync(0xffffffffu, v, o);
    return v;
}

// ---------------- Kernel: weight transpose+convert W[K,N] -> Wt[N,K] bf16 ----
__global__ __launch_bounds__(256) void wconv(
    const float* __restrict__ W, __nv_bfloat16* __restrict__ Wt, int K, int N)
{
    __shared__ float t[32][33];
    int nb = blockIdx.x * 32, kb = blockIdx.y * 32;
    int tx = threadIdx.x & 31, ty = threadIdx.x >> 5;
#pragma unroll
    for (int i = 0; i < 4; i++) t[ty + i*8][tx] = W[(size_t)(kb + ty + i*8) * N + nb + tx];
    __syncthreads();
#pragma unroll
    for (int i = 0; i < 4; i++)
        Wt[(size_t)(nb + ty + i*8) * K + kb + tx] = __float2bfloat16(t[tx][ty + i*8]);
}

// ---------------- Kernel 1: fused LN1 (+LN2 for asy rows) --------------------
__global__ __launch_bounds__(256) void ln_kernel(
    const float* __restrict__ x,
    const float* __restrict__ g1, const float* __restrict__ b1,
    const float* __restrict__ g2, const float* __restrict__ b2,
    float* __restrict__ out)
{
    int warp = threadIdx.x >> 5, lane = threadIdx.x & 31;
    int row = blockIdx.x * 8 + warp;
    const float* xr = x + (size_t)row * CDIM;
    int c0 = lane * 4;

    float v[8];
    {
        float4 a = *(const float4*)(xr + c0);
        float4 b = *(const float4*)(xr + 128 + c0);
        v[0]=a.x; v[1]=a.y; v[2]=a.z; v[3]=a.w; v[4]=b.x; v[5]=b.y; v[6]=b.z; v[7]=b.w;
    }
    float s = 0;
#pragma unroll
    for (int i = 0; i < 8; i++) s += v[i];
    float mu = wsum(s) * (1.f/256.f);
    float q = 0;
#pragma unroll
    for (int i = 0; i < 8; i++) { v[i] -= mu; q += v[i]*v[i]; }
    float rstd = rsqrtf(wsum(q) * (1.f/256.f) + LNEPS);

    float gg[8], bb[8];
    {
        float4 a = *(const float4*)(g1 + c0);
        float4 b = *(const float4*)(g1 + 128 + c0);
        gg[0]=a.x; gg[1]=a.y; gg[2]=a.z; gg[3]=a.w; gg[4]=b.x; gg[5]=b.y; gg[6]=b.z; gg[7]=b.w;
        float4 c = *(const float4*)(b1 + c0);
        float4 d = *(const float4*)(b1 + 128 + c0);
        bb[0]=c.x; bb[1]=c.y; bb[2]=c.z; bb[3]=c.w; bb[4]=d.x; bb[5]=d.y; bb[6]=d.z; bb[7]=d.w;
    }
    float y[8];
#pragma unroll
    for (int i = 0; i < 8; i++) y[i] = v[i]*rstd*gg[i] + bb[i];

    int p = row & 63, n = row >> 6;
    if (p >= ATOK) {
        float* o = out + (size_t)row * CDIM;
        *(float4*)(o + c0)       = make_float4(y[0],y[1],y[2],y[3]);
        *(float4*)(o + 128 + c0) = make_float4(y[4],y[5],y[6],y[7]);
    } else {
        float s2 = 0;
#pragma unroll
        for (int i = 0; i < 8; i++) s2 += y[i];
        float mu2 = wsum(s2) * (1.f/256.f);
        float q2 = 0;
#pragma unroll
        for (int i = 0; i < 8; i++) { y[i] -= mu2; q2 += y[i]*y[i]; }
        float rstd2 = rsqrtf(wsum(q2) * (1.f/256.f) + LNEPS);
        float g2v[8], b2v[8];
        {
            float4 a = *(const float4*)(g2 + c0);
            float4 b = *(const float4*)(g2 + 128 + c0);
            g2v[0]=a.x; g2v[1]=a.y; g2v[2]=a.z; g2v[3]=a.w; g2v[4]=b.x; g2v[5]=b.y; g2v[6]=b.z; g2v[7]=b.w;
            float4 c = *(const float4*)(b2 + c0);
            float4 d = *(const float4*)(b2 + 128 + c0);
            b2v[0]=c.x; b2v[1]=c.y; b2v[2]=c.z; b2v[3]=c.w; b2v[4]=d.x; b2v[5]=d.y; b2v[6]=d.z; b2v[7]=d.w;
        }
        float z[8];
#pragma unroll
        for (int i = 0; i < 8; i++) z[i] = y[i]*rstd2*g2v[i] + b2v[i];
        size_t ro = (size_t)n * ATOK + p;
        float* o = g_z + ro * CDIM;
        *(float4*)(o + c0)       = make_float4(z[0],z[1],z[2],z[3]);
        *(float4*)(o + 128 + c0) = make_float4(z[4],z[5],z[6],z[7]);
        __nv_bfloat16* ob = g_zb + ro * CDIM;
        *(__nv_bfloat162*)(ob + c0)       = __floats2bfloat162_rn(z[0], z[1]);
        *(__nv_bfloat162*)(ob + c0 + 2)   = __floats2bfloat162_rn(z[2], z[3]);
        *(__nv_bfloat162*)(ob + 128 + c0) = __floats2bfloat162_rn(z[4], z[5]);
        *(__nv_bfloat162*)(ob + 130 + c0) = __floats2bfloat162_rn(z[6], z[7]);
    }
}

// ---------------- Kernel 2: HMMA bf16 GEMM, 128x128 tile, warp 32x64 ---------
// C[M,N] = A[M,K] @ Wt^T (Wt is [N,K] K-major).
// EPI: 0 = +bias -> bf16 ; 1 = gelu(+bias) -> bf16 ;
//      2 = res + lsc*(+bias) -> fp32 + bf16 ; 3 = +bias -> fp32
template<int EPI>
__global__ __launch_bounds__(256) void hgemm(
    const __nv_bfloat16* __restrict__ A, const __nv_bfloat16* __restrict__ Bt,
    const float* __restrict__ bias, float* __restrict__ Cf,
    __nv_bfloat16* __restrict__ Cb, int K, int N,
    const float* __restrict__ res, const float* __restrict__ lsc)
{
    __shared__ __align__(128) char sA[2][128*64];   // [128 rows][32 bf16] swizzled
    __shared__ __align__(128) char sB[2][128*64];

    int tid = threadIdx.x, wid = tid >> 5, lane = tid & 31;
    int wm = wid & 3, wn = wid >> 2;       // warp tile: rows 32*wm.., cols 64*wn..
    int row0 = blockIdx.y << 7, col0 = blockIdx.x << 7;

    const __nv_bfloat16* Ag = A  + (size_t)row0 * K;
    const __nv_bfloat16* Bg = Bt + (size_t)col0 * K;

    uint32_t sAu = smem_u32(sA), sBu = smem_u32(sB);

    // cp.async fill of chunk kc into buffer kc&1
    int r0l = tid >> 2, c0l = tid & 3;           // first id
    uint32_t wo0 = swoff(r0l, c0l);
    uint32_t wo1 = swoff(r0l + 64, c0l);
    auto FILL = [&](int kc) {
        uint32_t ba = sAu + ((kc & 1) ? 128*64 : 0);
        uint32_t bb = sBu + ((kc & 1) ? 128*64 : 0);
        const __nv_bfloat16* ag = Ag + kc * 32;
        const __nv_bfloat16* bg = Bg + kc * 32;
        cpa16(ba + wo0, ag + (size_t)r0l * K + c0l * 8);
        cpa16(ba + wo1, ag + (size_t)(r0l + 64) * K + c0l * 8);
        cpa16(bb + wo0, bg + (size_t)r0l * K + c0l * 8);
        cpa16(bb + wo1, bg + (size_t)(r0l + 64) * K + c0l * 8);
        asm volatile("cp.async.commit_group;" ::: "memory");
    };

    float acc[2][8][4];
#pragma unroll
    for (int i = 0; i < 2; i++)
#pragma unroll
        for (int j = 0; j < 8; j++)
#pragma unroll
            for (int k = 0; k < 4; k++) acc[i][j][k] = 0.f;

    int NC = K >> 5;
    FILL(0); FILL(1);

    // ldmatrix address components (within-tile)
    int a_r = (lane & 15);                 // + wm*32 + mf*16
    int a_ch = lane >> 4;                  // + 2*ks
    int b_r = (lane & 7) + ((lane >> 4) << 3);   // + wn*64 + ng*16
    int b_ch = (lane >> 3) & 1;            // + 2*ks

    for (int kc = 0; kc < NC; kc++) {
        if (kc + 1 < NC) asm volatile("cp.async.wait_group 1;" ::: "memory");
        else             asm volatile("cp.async.wait_group 0;" ::: "memory");
        __syncthreads();

        uint32_t ba = sAu + ((kc & 1) ? 128*64 : 0);
        uint32_t bb = sBu + ((kc & 1) ? 128*64 : 0);
#pragma unroll
        for (int ks = 0; ks < 2; ks++) {
            uint32_t af[2][4], bf[4][4];
#pragma unroll
            for (int mf = 0; mf < 2; mf++)
                ldsm4(af[mf][0], af[mf][1], af[mf][2], af[mf][3],
                      ba + swoff(wm*32 + mf*16 + a_r, 2*ks + a_ch));
#pragma unroll
            for (int ng = 0; ng < 4; ng++)
                ldsm4(bf[ng][0], bf[ng][1], bf[ng][2], bf[ng][3],
                      bb + swoff(wn*64 + ng*16 + b_r, 2*ks + b_ch));
#pragma unroll
            for (int mf = 0; mf < 2; mf++)
#pragma unroll
                for (int ng = 0; ng < 4; ng++) {
                    mma16816(acc[mf][ng*2+0], af[mf], &bf[ng][0]);
                    mma16816(acc[mf][ng*2+1], af[mf], &bf[ng][2]);
                }
        }
        __syncthreads();
        if (kc + 2 < NC) FILL(kc + 2);
    }

    // ---------------- epilogue ----------------
    int qr = lane >> 2, qc = (lane & 3) * 2;
#pragma unroll
    for (int mf = 0; mf < 2; mf++) {
#pragma unroll
        for (int half = 0; half < 2; half++) {
            int row = row0 + wm*32 + mf*16 + qr + half*8;
            size_t rb = (size_t)row * N;
#pragma unroll
            for (int nf = 0; nf < 8; nf++) {
                int col = col0 + wn*64 + nf*8 + qc;
                float v0 = acc[mf][nf][half*2+0] + bias[col];
                float v1 = acc[mf][nf][half*2+1] + bias[col+1];
                if (EPI == 1) {
                    v0 = 0.5f*v0*(1.f + erff(v0*0.70710678118654752f));
                    v1 = 0.5f*v1*(1.f + erff(v1*0.70710678118654752f));
                } else if (EPI == 2) {
                    v0 = res[rb + col]   + lsc[col]   * v0;
                    v1 = res[rb + col+1] + lsc[col+1] * v1;
                    *(float2*)(Cf + rb + col) = make_float2(v0, v1);
                }
                if (EPI == 3) {
                    *(float2*)(Cf + rb + col) = make_float2(v0, v1);
                } else {
                    *(__nv_bfloat162*)(Cb + rb + col) = __floats2bfloat162_rn(v0, v1);
                }
            }
        }
    }
}

// ---------------- Kernel 3: per-(n,head) 48x48 attention (bf16 in/out) -------
__global__ __launch_bounds__(128) void attn_kernel(
    const __nv_bfloat16* __restrict__ qkv, __nv_bfloat16* __restrict__ ao)
{
    __shared__ float qs[48][33], ks[48][33], vs[48][33], S[48][49];
    int blk = blockIdx.x;
    int n = blk >> 3, h = blk & 7;
    int tid = threadIdx.x;
    const __nv_bfloat16* base = qkv + (size_t)n*ATOK*768 + h*96;

    for (int idx = tid; idx < 48*96; idx += 128) {
        int p = idx / 96, c = idx - p*96;
        float v = __bfloat162float(base[(size_t)p*768 + c]);
        if (c < 32)       qs[p][c]    = v;
        else if (c < 64)  ks[p][c-32] = v;
        else              vs[p][c-64] = v;
    }
    __syncthreads();

    {
        int ti = tid >> 3, tj = tid & 7;
        float acc[3][6] = {};
#pragma unroll
        for (int d = 0; d < 32; d++) {
            float aq[3], bk[6];
#pragma unroll
            for (int ii = 0; ii < 3; ii++) aq[ii] = qs[ti*3+ii][d];
#pragma unroll
            for (int jj = 0; jj < 6; jj++) bk[jj] = ks[tj*6+jj][d];
#pragma unroll
            for (int ii = 0; ii < 3; ii++)
#pragma unroll
                for (int jj = 0; jj < 6; jj++)
                    acc[ii][jj] = fmaf(aq[ii], bk[jj], acc[ii][jj]);
        }
#pragma unroll
        for (int ii = 0; ii < 3; ii++)
#pragma unroll
            for (int jj = 0; jj < 6; jj++)
                S[ti*3+ii][tj*6+jj] = acc[ii][jj] * QKSCALE;
    }
    __syncthreads();

    if (tid < 48) {
        float m = -1e30f;
#pragma unroll 4
        for (int j = 0; j < 48; j++) m = fmaxf(m, S[tid][j]);
        float s = 0.f;
#pragma unroll 4
        for (int j = 0; j < 48; j++) { float e = __expf(S[tid][j] - m); S[tid][j] = e; s += e; }
        float inv = 1.f / s;
#pragma unroll 4
        for (int j = 0; j < 48; j++) S[tid][j] *= inv;
    }
    __syncthreads();

    {
        int ti = tid >> 3, td = tid & 7;
        float acc[3][4] = {};
#pragma unroll 4
        for (int j = 0; j < 48; j++) {
            float sv[3], vv[4];
#pragma unroll
            for (int ii = 0; ii < 3; ii++) sv[ii] = S[ti*3+ii][j];
#pragma unroll
            for (int dd = 0; dd < 4; dd++) vv[dd] = vs[j][td*4+dd];
#pragma unroll
            for (int ii = 0; ii < 3; ii++)
#pragma unroll
                for (int dd = 0; dd < 4; dd++)
                    acc[ii][dd] = fmaf(sv[ii], vv[dd], acc[ii][dd]);
        }
#pragma unroll
        for (int ii = 0; ii < 3; ii++)
#pragma unroll
            for (int dd = 0; dd < 4; dd++)
                ao[((size_t)n*ATOK + ti*3+ii)*CDIM + h*DH + td*4+dd] =
                    __float2bfloat16(acc[ii][dd]);
    }
}

// ---------------- chunk means + final ----------------------------------------
__global__ __launch_bounds__(256) void chunk_partial(
    const float* __restrict__ mm, float* __restrict__ part)
{
    int b = blockIdx.y, s = blockIdx.x;
    int c = threadIdx.x;
    size_t r0 = (size_t)b * 12288 + (size_t)s * 384;
    float acc = 0.f;
    for (int r = 0; r < 384; r++) acc += mm[(r0 + r) * CDIM + c];
    part[((size_t)b*32 + s) * CDIM + c] = acc;
}

__global__ __launch_bounds__(256) void chunk_reduce(
    const float* __restrict__ part, float* __restrict__ cmean)
{
    int b = blockIdx.x, c = threadIdx.x;
    float a = 0.f;
#pragma unroll
    for (int s = 0; s < 32; s++) a += part[((size_t)b*32 + s) * CDIM + c];
    cmean[b*CDIM + c] = a * (1.f / 16384.f);
}

__global__ __launch_bounds__(256) void final_kernel(
    const float* __restrict__ xa, const float* __restrict__ mm,
    const float* __restrict__ cmean, const float* __restrict__ ls2,
    float* __restrict__ out)
{
    int row = blockIdx.x;
    int c = threadIdx.x;
    int n = row / ATOK, p = row - n * ATOK;
    int b = row / 12288;
    float m = 0.5f * mm[(size_t)row*CDIM + c] + 0.5f * cmean[b*CDIM + c];
    out[((size_t)n*LTOK + p)*CDIM + c] = xa[(size_t)row*CDIM + c] + ls2[c] * m;
}

// ---------------- host launch -------------------------------------------------
extern "C" void kernel_launch(void* const* d_in, const int* in_sizes, int n_in,
                              void* d_out, int out_size)
{
    const float* x      = (const float*)d_in[0];
    const float* n1g    = (const float*)d_in[8];
    const float* n1b    = (const float*)d_in[9];
    const float* n2g    = (const float*)d_in[10];
    const float* n2b    = (const float*)d_in[11];
    const float* qkvw   = (const float*)d_in[12];
    const float* qkvb   = (const float*)d_in[13];
    const float* projw  = (const float*)d_in[14];
    const float* projb  = (const float*)d_in[15];
    const float* ls1    = (const float*)d_in[16];
    const float* ls2    = (const float*)d_in[17];
    const float* w1     = (const float*)d_in[18];
    const float* b1     = (const float*)d_in[19];
    const float* w2     = (const float*)d_in[20];
    const float* b2     = (const float*)d_in[21];
    float* out = (float*)d_out;

    float *pz, *pxa, *pmm, *ppart, *pcmean;
    __nv_bfloat16 *pzb, *pqkv, *paob, *pxab, *ph1b, *pwq, *pwp, *pw1, *pw2;
    cudaGetSymbolAddress((void**)&pz,    g_z);
    cudaGetSymbolAddress((void**)&pzb,   g_zb);
    cudaGetSymbolAddress((void**)&pqkv,  g_qkv);
    cudaGetSymbolAddress((void**)&paob,  g_aob);
    cudaGetSymbolAddress((void**)&pxa,   g_xa);
    cudaGetSymbolAddress((void**)&pxab,  g_xab);
    cudaGetSymbolAddress((void**)&ph1b,  g_h1b);
    cudaGetSymbolAddress((void**)&pmm,   g_mm);
    cudaGetSymbolAddress((void**)&ppart, g_part);
    cudaGetSymbolAddress((void**)&pcmean,g_cmean);
    cudaGetSymbolAddress((void**)&pwq,   g_wqkvt);
    cudaGetSymbolAddress((void**)&pwp,   g_wprot);
    cudaGetSymbolAddress((void**)&pw1,   g_w1t);
    cudaGetSymbolAddress((void**)&pw2,   g_w2t);

    // 0) weight transpose+convert
    wconv<<<dim3(768/32, 256/32), 256>>>(qkvw, pwq, 256, 768);
    wconv<<<dim3(256/32, 256/32), 256>>>(projw, pwp, 256, 256);
    wconv<<<dim3(1024/32, 256/32), 256>>>(w1, pw1, 256, 1024);
    wconv<<<dim3(256/32, 1024/32), 256>>>(w2, pw2, 1024, 256);
    // 1) LN1 (+LN2 for asy rows)
    ln_kernel<<<16384, 256>>>(x, n1g, n1b, n2g, n2b, out);
    // 2) QKV GEMM -> bf16
    hgemm<0><<<dim3(6, 768), 256>>>(pzb, pwq, qkvb, nullptr, pqkv, 256, 768, nullptr, nullptr);
    // 3) attention
    attn_kernel<<<NWIN * HEADS, 128>>>(pqkv, paob);
    // 4) proj + residual/layerscale -> fp32 + bf16
    hgemm<2><<<dim3(2, 768), 256>>>(paob, pwp, projb, pxa, pxab, 256, 256, pz, ls1);
    // 5) MLP1 + gelu -> bf16
    hgemm<1><<<dim3(8, 768), 256>>>(pxab, pw1, b1, nullptr, ph1b, 256, 1024, nullptr, nullptr);
    // 6) MLP2 -> fp32
    hgemm<3><<<dim3(2, 768), 256>>>(ph1b, pw2, b2, pmm, nullptr, 1024, 256, nullptr, nullptr);
    // 7) chunk means
    chunk_partial<<<dim3(32, 8), 256>>>(pmm, ppart);
    chunk_reduce<<<8, 256>>>(ppart, pcmean);
    // 8) final combine
    final_kernel<<<AROWS, 256>>>(pxa, pmm, pcmean, ls2, out);
}

// round 4
// speedup vs baseline: 4.3565x; 1.1221x over previous
#include <cuda_runtime.h>
#include <cuda_bf16.h>
#include <math.h>
#include <stdint.h>

// Problem constants
#define NWIN  2048
#define LTOK  64
#define ATOK  48
#define CDIM  256
#define HEADS 8
#define DH    32
#define AROWS (NWIN*ATOK)       // 98304
#define QKSCALE 0.17677669529663687f
#define LNEPS 1e-5f
#define WSI   0.0625f           // 1/16 weight descale

// ---------------- scratch (device globals) -----------------------------------
__device__ float          g_z  [AROWS*CDIM];    // LN2 out fp32 (residual)
__device__ uint8_t        g_zq [AROWS*CDIM];    // LN2 out e4m3 (GEMM A)
__device__ __nv_bfloat16  g_qkv[AROWS*768];     // QKV out bf16 (attention)
__device__ uint8_t        g_aoq[AROWS*CDIM];    // attn out e4m3
__device__ float          g_xa [AROWS*CDIM];    // xa fp32
__device__ uint8_t        g_xaq[AROWS*CDIM];    // xa e4m3 (MLP A)
__device__ uint8_t        g_h1q[AROWS*1024];    // gelu(mlp1) e4m3
__device__ float          g_mm [AROWS*CDIM];    // mlp2 out fp32
__device__ float          g_part[8*32*CDIM];
__device__ float          g_cmean[8*CDIM];
// transposed e4m3 weights [N,K] (K-major), pre-scaled by 16
__device__ uint8_t        g_wqkvt[768*256];
__device__ uint8_t        g_wprot[256*256];
__device__ uint8_t        g_w1t  [1024*256];
__device__ uint8_t        g_w2t  [256*1024];

// ---------------- helpers ------------------------------------------------------
__device__ __forceinline__ uint32_t smem_u32(const void* p) {
    uint32_t a;
    asm("{ .reg .u64 t; cvta.to.shared.u64 t, %1; cvt.u32.u64 %0, t; }" : "=r"(a) : "l"(p));
    return a;
}
__device__ __forceinline__ void cpa16(uint32_t s, const void* g) {
    asm volatile("cp.async.cg.shared.global [%0], [%1], 16;" :: "r"(s), "l"(g) : "memory");
}
__device__ __forceinline__ void ldsm4(uint32_t& r0, uint32_t& r1, uint32_t& r2, uint32_t& r3,
                                      uint32_t addr) {
    asm volatile("ldmatrix.sync.aligned.m8n8.x4.shared.b16 {%0,%1,%2,%3}, [%4];"
        : "=r"(r0), "=r"(r1), "=r"(r2), "=r"(r3) : "r"(addr));
}
__device__ __forceinline__ void mma16816(float* d, const uint32_t* a, const uint32_t* b) {
    asm volatile(
        "mma.sync.aligned.m16n8k16.row.col.f32.bf16.bf16.f32 "
        "{%0,%1,%2,%3}, {%4,%5,%6,%7}, {%8,%9}, {%0,%1,%2,%3};"
        : "+f"(d[0]), "+f"(d[1]), "+f"(d[2]), "+f"(d[3])
        : "r"(a[0]), "r"(a[1]), "r"(a[2]), "r"(a[3]), "r"(b[0]), "r"(b[1]));
}
__device__ __forceinline__ void mma_e4m3(float* d, const uint32_t* a, const uint32_t* b) {
    asm volatile(
        "mma.sync.aligned.m16n8k32.row.col.f32.e4m3.e4m3.f32 "
        "{%0,%1,%2,%3}, {%4,%5,%6,%7}, {%8,%9}, {%0,%1,%2,%3};"
        : "+f"(d[0]), "+f"(d[1]), "+f"(d[2]), "+f"(d[3])
        : "r"(a[0]), "r"(a[1]), "r"(a[2]), "r"(a[3]), "r"(b[0]), "r"(b[1]));
}
// pack two floats -> e4m3x2 in a ushort (lo = first arg)
__device__ __forceinline__ uint32_t fp8x2(float lo, float hi) {
    uint16_t r;
    asm("cvt.rn.satfinite.e4m3x2.f32 %0, %1, %2;" : "=h"(r) : "f"(hi), "f"(lo));
    return (uint32_t)r;
}
__device__ __forceinline__ uint32_t bf16x2(float lo, float hi) {
    __nv_bfloat162 t = __floats2bfloat162_rn(lo, hi);
    return *(uint32_t*)&t;
}
// swizzled byte offset inside a [rows][64B] tile (4 x 16B chunks per row)
__device__ __forceinline__ uint32_t swoff(int r, int c) {
    return (uint32_t)(r * 64 + ((c ^ ((r >> 1) & 3)) << 4));
}
// swizzled byte offset inside a [rows][128B] tile (8 x 16B chunks per row)
__device__ __forceinline__ uint32_t vtoff(int r, int c) {
    return (uint32_t)(r * 128 + ((c ^ (r & 7)) << 4));
}
__device__ __forceinline__ float wsum(float v) {
#pragma unroll
    for (int o = 16; o > 0; o >>= 1) v += __shfl_xor_sync(0xffffffffu, v, o);
    return v;
}

// ---------------- weight transpose+convert W[K,N] -> Wt[N,K] e4m3 * 16 -------
__global__ __launch_bounds__(256) void wconv(
    const float* __restrict__ W, uint8_t* __restrict__ Wt, int K, int N)
{
    __shared__ float t[32][33];
    int nb = blockIdx.x * 32, kb = blockIdx.y * 32;
    int tx = threadIdx.x & 31, ty = threadIdx.x >> 5;
#pragma unroll
    for (int i = 0; i < 4; i++) t[ty + i*8][tx] = W[(size_t)(kb + ty + i*8) * N + nb + tx];
    __syncthreads();
#pragma unroll
    for (int i = 0; i < 4; i++)
        Wt[(size_t)(nb + ty + i*8) * K + kb + tx] =
            (uint8_t)(fp8x2(t[tx][ty + i*8] * 16.f, 0.f) & 0xff);
}

// ---------------- Kernel 1: fused LN1 (+LN2 for asy rows) --------------------
__global__ __launch_bounds__(256) void ln_kernel(
    const float* __restrict__ x,
    const float* __restrict__ g1, const float* __restrict__ b1,
    const float* __restrict__ g2, const float* __restrict__ b2,
    float* __restrict__ out)
{
    int warp = threadIdx.x >> 5, lane = threadIdx.x & 31;
    int row = blockIdx.x * 8 + warp;
    const float* xr = x + (size_t)row * CDIM;
    int c0 = lane * 4;

    float v[8];
    {
        float4 a = *(const float4*)(xr + c0);
        float4 b = *(const float4*)(xr + 128 + c0);
        v[0]=a.x; v[1]=a.y; v[2]=a.z; v[3]=a.w; v[4]=b.x; v[5]=b.y; v[6]=b.z; v[7]=b.w;
    }
    float s = 0;
#pragma unroll
    for (int i = 0; i < 8; i++) s += v[i];
    float mu = wsum(s) * (1.f/256.f);
    float q = 0;
#pragma unroll
    for (int i = 0; i < 8; i++) { v[i] -= mu; q += v[i]*v[i]; }
    float rstd = rsqrtf(wsum(q) * (1.f/256.f) + LNEPS);

    float gg[8], bb[8];
    {
        float4 a = *(const float4*)(g1 + c0);
        float4 b = *(const float4*)(g1 + 128 + c0);
        gg[0]=a.x; gg[1]=a.y; gg[2]=a.z; gg[3]=a.w; gg[4]=b.x; gg[5]=b.y; gg[6]=b.z; gg[7]=b.w;
        float4 c = *(const float4*)(b1 + c0);
        float4 d = *(const float4*)(b1 + 128 + c0);
        bb[0]=c.x; bb[1]=c.y; bb[2]=c.z; bb[3]=c.w; bb[4]=d.x; bb[5]=d.y; bb[6]=d.z; bb[7]=d.w;
    }
    float y[8];
#pragma unroll
    for (int i = 0; i < 8; i++) y[i] = v[i]*rstd*gg[i] + bb[i];

    int p = row & 63, n = row >> 6;
    if (p >= ATOK) {
        float* o = out + (size_t)row * CDIM;
        *(float4*)(o + c0)       = make_float4(y[0],y[1],y[2],y[3]);
        *(float4*)(o + 128 + c0) = make_float4(y[4],y[5],y[6],y[7]);
    } else {
        float s2 = 0;
#pragma unroll
        for (int i = 0; i < 8; i++) s2 += y[i];
        float mu2 = wsum(s2) * (1.f/256.f);
        float q2 = 0;
#pragma unroll
        for (int i = 0; i < 8; i++) { y[i] -= mu2; q2 += y[i]*y[i]; }
        float rstd2 = rsqrtf(wsum(q2) * (1.f/256.f) + LNEPS);
        float g2v[8], b2v[8];
        {
            float4 a = *(const float4*)(g2 + c0);
            float4 b = *(const float4*)(g2 + 128 + c0);
            g2v[0]=a.x; g2v[1]=a.y; g2v[2]=a.z; g2v[3]=a.w; g2v[4]=b.x; g2v[5]=b.y; g2v[6]=b.z; g2v[7]=b.w;
            float4 c = *(const float4*)(b2 + c0);
            float4 d = *(const float4*)(b2 + 128 + c0);
            b2v[0]=c.x; b2v[1]=c.y; b2v[2]=c.z; b2v[3]=c.w; b2v[4]=d.x; b2v[5]=d.y; b2v[6]=d.z; b2v[7]=d.w;
        }
        float z[8];
#pragma unroll
        for (int i = 0; i < 8; i++) z[i] = y[i]*rstd2*g2v[i] + b2v[i];
        size_t ro = (size_t)n * ATOK + p;
        float* o = g_z + ro * CDIM;
        *(float4*)(o + c0)       = make_float4(z[0],z[1],z[2],z[3]);
        *(float4*)(o + 128 + c0) = make_float4(z[4],z[5],z[6],z[7]);
        uint8_t* oq = g_zq + ro * CDIM;
        *(uint32_t*)(oq + c0)       = fp8x2(z[0],z[1]) | (fp8x2(z[2],z[3]) << 16);
        *(uint32_t*)(oq + 128 + c0) = fp8x2(z[4],z[5]) | (fp8x2(z[6],z[7]) << 16);
    }
}

// ---------------- Kernel 2: FP8 QMMA GEMM, 128x128 tile, warp 32x64 ----------
// C[M,N] = (A[M,K] @ Wt^T) * 1/16.  A, Wt are e4m3; Wt is [N,K] K-major.
// EPI: 0 = +bias -> bf16 ; 1 = gelu(+bias) -> fp8 ;
//      2 = res + lsc*(+bias) -> fp32 + fp8 ; 3 = +bias -> fp32
template<int EPI>
__global__ __launch_bounds__(256) void qgemm(
    const uint8_t* __restrict__ A, const uint8_t* __restrict__ Bt,
    const float* __restrict__ bias, float* __restrict__ Cf,
    __nv_bfloat16* __restrict__ Cb, uint8_t* __restrict__ Cq, int K, int N,
    const float* __restrict__ res, const float* __restrict__ lsc)
{
    __shared__ __align__(128) char sA[2][128*64];   // [128 rows][64 e4m3] swizzled
    __shared__ __align__(128) char sB[2][128*64];

    int tid = threadIdx.x, wid = tid >> 5, lane = tid & 31;
    int wm = wid & 3, wn = wid >> 2;
    int row0 = blockIdx.y << 7, col0 = blockIdx.x << 7;

    const uint8_t* Ag = A  + (size_t)row0 * K;
    const uint8_t* Bg = Bt + (size_t)col0 * K;

    uint32_t sAu = smem_u32(sA), sBu = smem_u32(sB);

    int r0l = tid >> 2, c0l = tid & 3;
    uint32_t wo0 = swoff(r0l, c0l);
    uint32_t wo1 = swoff(r0l + 64, c0l);
    auto FILL = [&](int kc) {
        uint32_t ba = sAu + ((kc & 1) ? 128*64 : 0);
        uint32_t bb = sBu + ((kc & 1) ? 128*64 : 0);
        const uint8_t* ag = Ag + kc * 64;
        const uint8_t* bg = Bg + kc * 64;
        cpa16(ba + wo0, ag + (size_t)r0l * K + c0l * 16);
        cpa16(ba + wo1, ag + (size_t)(r0l + 64) * K + c0l * 16);
        cpa16(bb + wo0, bg + (size_t)r0l * K + c0l * 16);
        cpa16(bb + wo1, bg + (size_t)(r0l + 64) * K + c0l * 16);
        asm volatile("cp.async.commit_group;" ::: "memory");
    };

    float acc[2][8][4];
#pragma unroll
    for (int i = 0; i < 2; i++)
#pragma unroll
        for (int j = 0; j < 8; j++)
#pragma unroll
            for (int k = 0; k < 4; k++) acc[i][j][k] = 0.f;

    int NC = K >> 6;
    FILL(0); FILL(1);

    int a_r = (lane & 15);
    int a_ch = lane >> 4;
    int b_r = (lane & 7) + ((lane >> 4) << 3);
    int b_ch = (lane >> 3) & 1;

    for (int kc = 0; kc < NC; kc++) {
        if (kc + 1 < NC) asm volatile("cp.async.wait_group 1;" ::: "memory");
        else             asm volatile("cp.async.wait_group 0;" ::: "memory");
        __syncthreads();

        uint32_t ba = sAu + ((kc & 1) ? 128*64 : 0);
        uint32_t bb = sBu + ((kc & 1) ? 128*64 : 0);
#pragma unroll
        for (int ks = 0; ks < 2; ks++) {   // 2 x k32 per 64-elem chunk
            uint32_t af[2][4], bf[4][4];
#pragma unroll
            for (int mf = 0; mf < 2; mf++)
                ldsm4(af[mf][0], af[mf][1], af[mf][2], af[mf][3],
                      ba + swoff(wm*32 + mf*16 + a_r, 2*ks + a_ch));
#pragma unroll
            for (int ng = 0; ng < 4; ng++)
                ldsm4(bf[ng][0], bf[ng][1], bf[ng][2], bf[ng][3],
                      bb + swoff(wn*64 + ng*16 + b_r, 2*ks + b_ch));
#pragma unroll
            for (int mf = 0; mf < 2; mf++)
#pragma unroll
                for (int ng = 0; ng < 4; ng++) {
                    mma_e4m3(acc[mf][ng*2+0], af[mf], &bf[ng][0]);
                    mma_e4m3(acc[mf][ng*2+1], af[mf], &bf[ng][2]);
                }
        }
        __syncthreads();
        if (kc + 2 < NC) FILL(kc + 2);
    }

    // ---------------- epilogue ----------------
    int qr = lane >> 2, qc = (lane & 3) * 2;
#pragma unroll
    for (int mf = 0; mf < 2; mf++) {
#pragma unroll
        for (int half = 0; half < 2; half++) {
            int row = row0 + wm*32 + mf*16 + qr + half*8;
            size_t rb = (size_t)row * N;
#pragma unroll
            for (int nf = 0; nf < 8; nf++) {
                int col = col0 + wn*64 + nf*8 + qc;
                float v0 = fmaf(acc[mf][nf][half*2+0], WSI, bias[col]);
                float v1 = fmaf(acc[mf][nf][half*2+1], WSI, bias[col+1]);
                if (EPI == 0) {
                    *(uint32_t*)(Cb + rb + col) = bf16x2(v0, v1);
                } else if (EPI == 1) {
                    v0 = 0.5f*v0*(1.f + erff(v0*0.70710678118654752f));
                    v1 = 0.5f*v1*(1.f + erff(v1*0.70710678118654752f));
                    *(uint16_t*)(Cq + rb + col) = (uint16_t)fp8x2(v0, v1);
                } else if (EPI == 2) {
                    v0 = res[rb + col]   + lsc[col]   * v0;
                    v1 = res[rb + col+1] + lsc[col+1] * v1;
                    *(float2*)(Cf + rb + col) = make_float2(v0, v1);
                    *(uint16_t*)(Cq + rb + col) = (uint16_t)fp8x2(v0, v1);
                } else {
                    *(float2*)(Cf + rb + col) = make_float2(v0, v1);
                }
            }
        }
    }
}

// ---------------- Kernel 3: HMMA attention, 1 warp per (n, head) -------------
// S = QK^T*scale (bf16 mma) -> softmax in regs -> P (in-reg bf16 A-frags) -> PV
__global__ __launch_bounds__(128) void attn_kernel(
    const __nv_bfloat16* __restrict__ qkv, uint8_t* __restrict__ aoq)
{
    __shared__ __align__(16) char sq[4][48*64];   // Q  48 rows x 64B, swoff
    __shared__ __align__(16) char sk[4][48*64];   // K  48 rows x 64B, swoff
    __shared__ __align__(16) char sv[4][32*128];  // V^T 32 rows x 128B, vtoff

    int wid = threadIdx.x >> 5, lane = threadIdx.x & 31;
    int n = blockIdx.x >> 1, hg = blockIdx.x & 1;
    int h = hg * 4 + wid;
    const char* base = (const char*)qkv + ((size_t)n*ATOK*768 + h*96) * 2;

    // load Q, K (row stride 1536B)
    for (int i = lane; i < 192; i += 32) {
        int p = i >> 2, c = i & 3;
        const char* rp = base + (size_t)p * 1536;
        *(uint4*)(sq[wid] + swoff(p, c)) = *(const uint4*)(rp + c*16);
        *(uint4*)(sk[wid] + swoff(p, c)) = *(const uint4*)(rp + 64 + c*16);
    }
    // load V transposed: V[p][d] -> Vt[d][p]
    for (int i = lane; i < 768; i += 32) {
        int p = i >> 4, dp = (i & 15) * 2;
        uint32_t v = *(const uint32_t*)(base + (size_t)p * 1536 + 128 + dp*2);
        int cc = p >> 3, ib = (p & 7) * 2;
        *(uint16_t*)(sv[wid] + (dp    )*128 + ((cc ^ ( dp      & 7)) << 4) + ib) = (uint16_t)(v & 0xffff);
        *(uint16_t*)(sv[wid] + (dp + 1)*128 + ((cc ^ ((dp + 1) & 7)) << 4) + ib) = (uint16_t)(v >> 16);
    }
    __syncwarp();

    uint32_t q_s = smem_u32(sq[wid]), k_s = smem_u32(sk[wid]), v_s = smem_u32(sv[wid]);
    int a_r = lane & 15, a_ch = lane >> 4;
    int b_r = (lane & 7) + ((lane >> 4) << 3);
    int b_ch = (lane >> 3) & 1;

    // S = Q K^T : M=48(3 frags), N=48(6 frags), K=32(2 steps)
    float s[3][6][4];
#pragma unroll
    for (int i = 0; i < 3; i++)
#pragma unroll
        for (int j = 0; j < 6; j++)
#pragma unroll
            for (int e = 0; e < 4; e++) s[i][j][e] = 0.f;

#pragma unroll
    for (int ks = 0; ks < 2; ks++) {
        uint32_t af[3][4];
#pragma unroll
        for (int mf = 0; mf < 3; mf++)
            ldsm4(af[mf][0], af[mf][1], af[mf][2], af[mf][3],
                  q_s + swoff(mf*16 + a_r, 2*ks + a_ch));
#pragma unroll
        for (int ng = 0; ng < 3; ng++) {
            uint32_t bf[4];
            ldsm4(bf[0], bf[1], bf[2], bf[3],
                  k_s + swoff(ng*16 + b_r, 2*ks + b_ch));
#pragma unroll
            for (int mf = 0; mf < 3; mf++) {
                mma16816(s[mf][ng*2+0], af[mf], &bf[0]);
                mma16816(s[mf][ng*2+1], af[mf], &bf[2]);
            }
        }
    }

    // softmax over 48 keys; rows qr & qr+8 per m-frag; quad = lanes sharing qr
    float inv[3][2];
    uint32_t pa[3][3][4];   // P as bf16 A-frags (k=48 -> 3 frags)
#pragma unroll
    for (int mf = 0; mf < 3; mf++) {
        float mx0 = -1e30f, mx1 = -1e30f;
#pragma unroll
        for (int nf = 0; nf < 6; nf++) {
#pragma unroll
            for (int e = 0; e < 4; e++) s[mf][nf][e] *= QKSCALE;
            mx0 = fmaxf(mx0, fmaxf(s[mf][nf][0], s[mf][nf][1]));
            mx1 = fmaxf(mx1, fmaxf(s[mf][nf][2], s[mf][nf][3]));
        }
        mx0 = fmaxf(mx0, __shfl_xor_sync(0xffffffffu, mx0, 1));
        mx0 = fmaxf(mx0, __shfl_xor_sync(0xffffffffu, mx0, 2));
        mx1 = fmaxf(mx1, __shfl_xor_sync(0xffffffffu, mx1, 1));
        mx1 = fmaxf(mx1, __shfl_xor_sync(0xffffffffu, mx1, 2));
        float sm0 = 0.f, sm1 = 0.f;
#pragma unroll
        for (int nf = 0; nf < 6; nf++) {
            s[mf][nf][0] = __expf(s[mf][nf][0] - mx0);
            s[mf][nf][1] = __expf(s[mf][nf][1] - mx0);
            s[mf][nf][2] = __expf(s[mf][nf][2] - mx1);
            s[mf][nf][3] = __expf(s[mf][nf][3] - mx1);
            sm0 += s[mf][nf][0] + s[mf][nf][1];
            sm1 += s[mf][nf][2] + s[mf][nf][3];
        }
        sm0 += __shfl_xor_sync(0xffffffffu, sm0, 1);
        sm0 += __shfl_xor_sync(0xffffffffu, sm0, 2);
        sm1 += __shfl_xor_sync(0xffffffffu, sm1, 1);
        sm1 += __shfl_xor_sync(0xffffffffu, sm1, 2);
        inv[mf][0] = 1.f / sm0;
        inv[mf][1] = 1.f / sm1;
        // C-frag -> A-frag identity: kf uses n-frags 2kf, 2kf+1
#pragma unroll
        for (int kf = 0; kf < 3; kf++) {
            pa[mf][kf][0] = bf16x2(s[mf][2*kf  ][0], s[mf][2*kf  ][1]);
            pa[mf][kf][1] = bf16x2(s[mf][2*kf  ][2], s[mf][2*kf  ][3]);
            pa[mf][kf][2] = bf16x2(s[mf][2*kf+1][0], s[mf][2*kf+1][1]);
            pa[mf][kf][3] = bf16x2(s[mf][2*kf+1][2], s[mf][2*kf+1][3]);
        }
    }

    // O = P V : M=48, N=32(4 frags), K=48(3 steps)
    float o[3][4][4];
#pragma unroll
    for (int i = 0; i < 3; i++)
#pragma unroll
        for (int j = 0; j < 4; j++)
#pragma unroll
            for (int e = 0; e < 4; e++) o[i][j][e] = 0.f;

#pragma unroll
    for (int kf = 0; kf < 3; kf++) {
#pragma unroll
        for (int ng = 0; ng < 2; ng++) {
            uint32_t bf[4];
            ldsm4(bf[0], bf[1], bf[2], bf[3],
                  v_s + vtoff(ng*16 + b_r, 2*kf + b_ch));
#pragma unroll
            for (int mf = 0; mf < 3; mf++) {
                mma16816(o[mf][ng*2+0], pa[mf][kf], &bf[0]);
                mma16816(o[mf][ng*2+1], pa[mf][kf], &bf[2]);
            }
        }
    }

    // write O (normalized) as e4m3 to aoq[row][h*32 + d]
    int qr = lane >> 2, t2 = (lane & 3) * 2;
#pragma unroll
    for (int mf = 0; mf < 3; mf++) {
        size_t r0 = (size_t)(n*ATOK + mf*16 + qr) * CDIM;
        size_t r1 = r0 + 8*CDIM;
#pragma unroll
        for (int nf = 0; nf < 4; nf++) {
            int col = h*32 + nf*8 + t2;
            *(uint16_t*)(aoq + r0 + col) =
                (uint16_t)fp8x2(o[mf][nf][0]*inv[mf][0], o[mf][nf][1]*inv[mf][0]);
            *(uint16_t*)(aoq + r1 + col) =
                (uint16_t)fp8x2(o[mf][nf][2]*inv[mf][1], o[mf][nf][3]*inv[mf][1]);
        }
    }
}

// ---------------- chunk means + final ----------------------------------------
__global__ __launch_bounds__(256) void chunk_partial(
    const float* __restrict__ mm, float* __restrict__ part)
{
    int b = blockIdx.y, s = blockIdx.x;
    int c = threadIdx.x;
    size_t r0 = (size_t)b * 12288 + (size_t)s * 384;
    float acc = 0.f;
    for (int r = 0; r < 384; r++) acc += mm[(r0 + r) * CDIM + c];
    part[((size_t)b*32 + s) * CDIM + c] = acc;
}

__global__ __launch_bounds__(256) void chunk_reduce(
    const float* __restrict__ part, float* __restrict__ cmean)
{
    int b = blockIdx.x, c = threadIdx.x;
    float a = 0.f;
#pragma unroll
    for (int s = 0; s < 32; s++) a += part[((size_t)b*32 + s) * CDIM + c];
    cmean[b*CDIM + c] = a * (1.f / 16384.f);
}

__global__ __launch_bounds__(256) void final_kernel(
    const float* __restrict__ xa, const float* __restrict__ mm,
    const float* __restrict__ cmean, const float* __restrict__ ls2,
    float* __restrict__ out)
{
    int row = blockIdx.x;
    int c = threadIdx.x;
    int n = row / ATOK, p = row - n * ATOK;
    int b = row / 12288;
    float m = 0.5f * mm[(size_t)row*CDIM + c] + 0.5f * cmean[b*CDIM + c];
    out[((size_t)n*LTOK + p)*CDIM + c] = xa[(size_t)row*CDIM + c] + ls2[c] * m;
}

// ---------------- host launch -------------------------------------------------
extern "C" void kernel_launch(void* const* d_in, const int* in_sizes, int n_in,
                              void* d_out, int out_size)
{
    const float* x      = (const float*)d_in[0];
    const float* n1g    = (const float*)d_in[8];
    const float* n1b    = (const float*)d_in[9];
    const float* n2g    = (const float*)d_in[10];
    const float* n2b    = (const float*)d_in[11];
    const float* qkvw   = (const float*)d_in[12];
    const float* qkvb   = (const float*)d_in[13];
    const float* projw  = (const float*)d_in[14];
    const float* projb  = (const float*)d_in[15];
    const float* ls1    = (const float*)d_in[16];
    const float* ls2    = (const float*)d_in[17];
    const float* w1     = (const float*)d_in[18];
    const float* b1     = (const float*)d_in[19];
    const float* w2     = (const float*)d_in[20];
    const float* b2     = (const float*)d_in[21];
    float* out = (float*)d_out;

    float *pz, *pxa, *pmm, *ppart, *pcmean;
    __nv_bfloat16 *pqkv;
    uint8_t *pzq, *paoq, *pxaq, *ph1q, *pwq, *pwp, *pw1, *pw2;
    cudaGetSymbolAddress((void**)&pz,    g_z);
    cudaGetSymbolAddress((void**)&pzq,   g_zq);
    cudaGetSymbolAddress((void**)&pqkv,  g_qkv);
    cudaGetSymbolAddress((void**)&paoq,  g_aoq);
    cudaGetSymbolAddress((void**)&pxa,   g_xa);
    cudaGetSymbolAddress((void**)&pxaq,  g_xaq);
    cudaGetSymbolAddress((void**)&ph1q,  g_h1q);
    cudaGetSymbolAddress((void**)&pmm,   g_mm);
    cudaGetSymbolAddress((void**)&ppart, g_part);
    cudaGetSymbolAddress((void**)&pcmean,g_cmean);
    cudaGetSymbolAddress((void**)&pwq,   g_wqkvt);
    cudaGetSymbolAddress((void**)&pwp,   g_wprot);
    cudaGetSymbolAddress((void**)&pw1,   g_w1t);
    cudaGetSymbolAddress((void**)&pw2,   g_w2t);

    // 0) weight transpose+convert (x16 scale)
    wconv<<<dim3(768/32, 256/32), 256>>>(qkvw, pwq, 256, 768);
    wconv<<<dim3(256/32, 256/32), 256>>>(projw, pwp, 256, 256);
    wconv<<<dim3(1024/32, 256/32), 256>>>(w1, pw1, 256, 1024);
    wconv<<<dim3(256/32, 1024/32), 256>>>(w2, pw2, 1024, 256);
    // 1) LN1 (+LN2 for asy rows)
    ln_kernel<<<16384, 256>>>(x, n1g, n1b, n2g, n2b, out);
    // 2) QKV GEMM -> bf16
    qgemm<0><<<dim3(6, 768), 256>>>(pzq, pwq, qkvb, nullptr, pqkv, nullptr, 256, 768, nullptr, nullptr);
    // 3) attention (HMMA) -> fp8
    attn_kernel<<<NWIN * 2, 128>>>(pqkv, paoq);
    // 4) proj + residual/layerscale -> fp32 + fp8
    qgemm<2><<<dim3(2, 768), 256>>>(paoq, pwp, projb, pxa, nullptr, pxaq, 256, 256, pz, ls1);
    // 5) MLP1 + gelu -> fp8
    qgemm<1><<<dim3(8, 768), 256>>>(pxaq, pw1, b1, nullptr, nullptr, ph1q, 256, 1024, nullptr, nullptr);
    // 6) MLP2 -> fp32
    qgemm<3><<<dim3(2, 768), 256>>>(ph1q, pw2, b2, pmm, nullptr, nullptr, 1024, 256, nullptr, nullptr);
    // 7) chunk means
    chunk_partial<<<dim3(32, 8), 256>>>(pmm, ppart);
    chunk_reduce<<<8, 256>>>(ppart, pcmean);
    // 8) final combine
    final_kernel<<<AROWS, 256>>>(pxa, pmm, pcmean, ls2, out);
}